// round 5
// baseline (speedup 1.0000x reference)
#include <cuda_runtime.h>

// BranchRoute: score = sigmoid(x @ gate_w + gate_b); mask_i = score_i > 0.5
// out = concat(x*m0, x*m1, x*(m0+m1)), each [N, D] fp32.
// sigmoid(z) > 0.5 <=> z > 0, so only the dot-product sign matters.
//
// R5: software-pipelined prefetch. Next row's 4 LDG.128 issue at the TOP of
// each iteration, overlapping their DRAM latency with the current row's
// dot/reduce/barrier/store phase. gate_w moves from a 32-reg cache to shared
// memory planes ws0/ws1 (8 conflict-free LDS.128 per row per thread) to pay
// for the prefetch registers. 4 blocks/SM (regs<=64, smem 32.9KB), grid=592
// = exactly the resident set.

#define THREADS 256
#define DIM 4096

__global__ void __launch_bounds__(THREADS, 4)
branch_route_kernel(const float* __restrict__ x,
                    const float* __restrict__ gw,   // [D, 2]
                    const float* __restrict__ gb,   // [2]
                    float* __restrict__ out,        // [3, N, D]
                    int N)
{
    const int t = threadIdx.x;

    __shared__ float ws0[DIM];     // gate_w[:,0]
    __shared__ float ws1[DIM];     // gate_w[:,1]
    __shared__ float2 red[2][8];   // [parity][warp] partial (s0, s1)

    // Stage gate_w into shared (once per block).
    const float2* gwv = (const float2*)gw;
#pragma unroll
    for (int i = 0; i < DIM / THREADS; i++) {
        int col = i * THREADS + t;
        float2 g = gwv[col];
        ws0[col] = g.x;
        ws1[col] = g.y;
    }
    const float b0 = gb[0];
    const float b1 = gb[1];
    __syncthreads();

    float* __restrict__ o0 = out;
    float* __restrict__ o1 = out + (size_t)N * DIM;
    float* __restrict__ oc = out + (size_t)2 * N * DIM;

    const float4* __restrict__ xv = (const float4*)x;
    const int stride = gridDim.x;

    int row = blockIdx.x;
    if (row >= N) return;

    // Prologue: load first row.
    float4 v[4];
    {
        const size_t base = (size_t)row * (DIM / 4);
#pragma unroll
        for (int c = 0; c < 4; c++) v[c] = xv[base + c * 256 + t];
    }

    int parity = 0;
    for (; row < N; row += stride, parity ^= 1) {
        const int next = row + stride;

        // Prefetch next row FIRST: latency overlaps everything below.
        float4 vn[4];
        if (next < N) {
            const size_t nbase = (size_t)next * (DIM / 4);
#pragma unroll
            for (int c = 0; c < 4; c++) vn[c] = xv[nbase + c * 256 + t];
        }

        // Partial dots: weights from shared (conflict-free LDS.128).
        float s0 = 0.f, s1 = 0.f;
#pragma unroll
        for (int c = 0; c < 4; c++) {
            const int col = c * 1024 + t * 4;
            const float4 w0 = *(const float4*)&ws0[col];
            const float4 w1 = *(const float4*)&ws1[col];
            s0 = fmaf(v[c].x, w0.x, s0);  s1 = fmaf(v[c].x, w1.x, s1);
            s0 = fmaf(v[c].y, w0.y, s0);  s1 = fmaf(v[c].y, w1.y, s1);
            s0 = fmaf(v[c].z, w0.z, s0);  s1 = fmaf(v[c].z, w1.z, s1);
            s0 = fmaf(v[c].w, w0.w, s0);  s1 = fmaf(v[c].w, w1.w, s1);
        }

        // Warp butterfly reduce.
#pragma unroll
        for (int o = 16; o > 0; o >>= 1) {
            s0 += __shfl_xor_sync(0xffffffffu, s0, o);
            s1 += __shfl_xor_sync(0xffffffffu, s1, o);
        }
        if ((t & 31) == 0) red[parity][t >> 5] = make_float2(s0, s1);
        __syncthreads();   // single barrier per row (double-buffered shared)

        float d0 = b0, d1 = b1;
#pragma unroll
        for (int k = 0; k < 8; k++) {
            d0 += red[parity][k].x;
            d1 += red[parity][k].y;
        }

        const float f0 = d0 > 0.f ? 1.f : 0.f;
        const float f1 = d1 > 0.f ? 1.f : 0.f;
        const float fc = f0 + f1;

        const size_t base = (size_t)row * (DIM / 4);
        float4* __restrict__ p0 = (float4*)o0 + base;
        float4* __restrict__ p1 = (float4*)o1 + base;
        float4* __restrict__ pc = (float4*)oc + base;

#pragma unroll
        for (int c = 0; c < 4; c++) {
            const int idx = c * 256 + t;
            float4 a, b, s;
            a.x = f0 * v[c].x; a.y = f0 * v[c].y; a.z = f0 * v[c].z; a.w = f0 * v[c].w;
            b.x = f1 * v[c].x; b.y = f1 * v[c].y; b.z = f1 * v[c].z; b.w = f1 * v[c].w;
            s.x = fc * v[c].x; s.y = fc * v[c].y; s.z = fc * v[c].z; s.w = fc * v[c].w;
            __stcs(&p0[idx], a);
            __stcs(&p1[idx], b);
            __stcs(&pc[idx], s);
        }

        // Rotate pipeline.
#pragma unroll
        for (int c = 0; c < 4; c++) v[c] = vn[c];
    }
}

extern "C" void kernel_launch(void* const* d_in, const int* in_sizes, int n_in,
                              void* d_out, int out_size)
{
    const float* x  = (const float*)d_in[0];
    const float* gw = (const float*)d_in[1];
    const float* gb = (const float*)d_in[2];
    float* out = (float*)d_out;

    const int N = in_sizes[0] / DIM;   // 8192

    const int grid = 148 * 4;          // exactly the resident set (4 blocks/SM)
    branch_route_kernel<<<grid, THREADS>>>(x, gw, gb, out, N);
}

// round 6
// speedup vs baseline: 1.0718x; 1.0718x over previous
#include <cuda_runtime.h>
#include <cstdint>

// BranchRoute: score = sigmoid(x @ gate_w + gate_b); mask_i = score_i > 0.5
// out = concat(x*m0, x*m1, x*(m0+m1)), each [N, D] fp32.
// sigmoid(z) > 0.5 <=> z > 0, so only the dot-product sign matters.
//
// R6: TMA bulk stores. All prior rounds emit the 384MiB write stream as
// per-warp 512B STG bursts round-robined over 3 regions -> fragmented DRAM
// write pattern stuck at ~73% of HBM. Here each block stages the 3 scaled
// 16KB output rows in SMEM and ONE thread issues 3x
// cp.async.bulk.global.shared::cta (UBLKCP): contiguous 16KB DRAM write
// bursts from the TMA engine, double-buffered so row i's writes overlap
// row i+1's loads/dot. Loads remain LDG->registers (R1 dot structure,
// register-cached gate_w).

#define THREADS 256
#define DIM 4096
#define ROW_BYTES (DIM * 4)          // 16384

__device__ __forceinline__ uint32_t smem_u32(const void* p) {
    uint32_t a;
    asm("{ .reg .u64 t; cvta.to.shared.u64 t, %1; cvt.u32.u64 %0, t; }"
        : "=r"(a) : "l"(p));
    return a;
}

__global__ void __launch_bounds__(THREADS, 2)
branch_route_kernel(const float* __restrict__ x,
                    const float* __restrict__ gw,   // [D, 2]
                    const float* __restrict__ gb,   // [2]
                    float* __restrict__ out,        // [3, N, D]
                    int N)
{
    extern __shared__ char smem_raw[];
    // staging: [parity][output][DIM floats]  = 2*3*16KB = 96KB
    float4* stage = (float4*)smem_raw;
    float2* red   = (float2*)(smem_raw + 2 * 3 * ROW_BYTES);  // [parity*8+warp]

    const int t = threadIdx.x;

    // Register cache of this thread's 16 gate_w pairs.
    float2 w[16];
#pragma unroll
    for (int c = 0; c < 4; c++)
#pragma unroll
        for (int j = 0; j < 4; j++)
            w[c * 4 + j] = ((const float2*)gw)[c * 1024 + t * 4 + j];
    const float b0 = gb[0];
    const float b1 = gb[1];

    float* __restrict__ o0 = out;
    float* __restrict__ o1 = out + (size_t)N * DIM;
    float* __restrict__ oc = out + (size_t)2 * N * DIM;

    const float4* __restrict__ xv = (const float4*)x;

    int parity = 0;
    for (int row = blockIdx.x; row < N; row += gridDim.x, parity ^= 1) {
        const size_t base = (size_t)row * (DIM / 4);

        // Load row (coalesced LDG.128), keep in registers.
        float4 v[4];
#pragma unroll
        for (int c = 0; c < 4; c++) v[c] = xv[base + c * 256 + t];

        // Ensure the staging buffer for this parity is no longer being read
        // by an in-flight bulk copy (>=2 groups ago). Thread 0 tracks groups;
        // the upcoming __syncthreads orders this before anyone's STS.
        if (t == 0)
            asm volatile("cp.async.bulk.wait_group.read 1;" ::: "memory");

        // Partial dots for both gate columns.
        float s0 = 0.f, s1 = 0.f;
#pragma unroll
        for (int c = 0; c < 4; c++) {
            s0 = fmaf(v[c].x, w[c*4+0].x, s0);  s1 = fmaf(v[c].x, w[c*4+0].y, s1);
            s0 = fmaf(v[c].y, w[c*4+1].x, s0);  s1 = fmaf(v[c].y, w[c*4+1].y, s1);
            s0 = fmaf(v[c].z, w[c*4+2].x, s0);  s1 = fmaf(v[c].z, w[c*4+2].y, s1);
            s0 = fmaf(v[c].w, w[c*4+3].x, s0);  s1 = fmaf(v[c].w, w[c*4+3].y, s1);
        }
#pragma unroll
        for (int o = 16; o > 0; o >>= 1) {
            s0 += __shfl_xor_sync(0xffffffffu, s0, o);
            s1 += __shfl_xor_sync(0xffffffffu, s1, o);
        }
        if ((t & 31) == 0) red[parity * 8 + (t >> 5)] = make_float2(s0, s1);
        __syncthreads();   // B1: reduce ready + wait_group ordered

        float d0 = b0, d1 = b1;
#pragma unroll
        for (int k = 0; k < 8; k++) {
            d0 += red[parity * 8 + k].x;
            d1 += red[parity * 8 + k].y;
        }
        const float f0 = d0 > 0.f ? 1.f : 0.f;
        const float f1 = d1 > 0.f ? 1.f : 0.f;
        const float fc = f0 + f1;

        // Stage 3 scaled rows into SMEM (conflict-free STS.128).
        float4* s0p = stage + (parity * 3 + 0) * (DIM / 4);
        float4* s1p = stage + (parity * 3 + 1) * (DIM / 4);
        float4* scp = stage + (parity * 3 + 2) * (DIM / 4);
#pragma unroll
        for (int c = 0; c < 4; c++) {
            const int idx = c * 256 + t;
            float4 a, b, s;
            a.x = f0*v[c].x; a.y = f0*v[c].y; a.z = f0*v[c].z; a.w = f0*v[c].w;
            b.x = f1*v[c].x; b.y = f1*v[c].y; b.z = f1*v[c].z; b.w = f1*v[c].w;
            s.x = fc*v[c].x; s.y = fc*v[c].y; s.z = fc*v[c].z; s.w = fc*v[c].w;
            s0p[idx] = a;
            s1p[idx] = b;
            scp[idx] = s;
        }
        // Order generic-proxy STS before async-proxy bulk reads.
        asm volatile("fence.proxy.async.shared::cta;" ::: "memory");
        __syncthreads();   // B2: staging complete, visible CTA-wide

        // One thread issues 3 bulk copies (16KB each) + commit.
        if (t == 0) {
            uint32_t sa0 = smem_u32(s0p);
            uint32_t sa1 = smem_u32(s1p);
            uint32_t sac = smem_u32(scp);
            asm volatile(
                "cp.async.bulk.global.shared::cta.bulk_group [%0], [%1], %2;"
                :: "l"(o0 + (size_t)row * DIM), "r"(sa0), "r"(ROW_BYTES) : "memory");
            asm volatile(
                "cp.async.bulk.global.shared::cta.bulk_group [%0], [%1], %2;"
                :: "l"(o1 + (size_t)row * DIM), "r"(sa1), "r"(ROW_BYTES) : "memory");
            asm volatile(
                "cp.async.bulk.global.shared::cta.bulk_group [%0], [%1], %2;"
                :: "l"(oc + (size_t)row * DIM), "r"(sac), "r"(ROW_BYTES) : "memory");
            asm volatile("cp.async.bulk.commit_group;" ::: "memory");
        }
    }

    // Drain all outstanding bulk stores before exit.
    if (t == 0)
        asm volatile("cp.async.bulk.wait_group 0;" ::: "memory");
}

extern "C" void kernel_launch(void* const* d_in, const int* in_sizes, int n_in,
                              void* d_out, int out_size)
{
    const float* x  = (const float*)d_in[0];
    const float* gw = (const float*)d_in[1];
    const float* gb = (const float*)d_in[2];
    float* out = (float*)d_out;

    const int N = in_sizes[0] / DIM;   // 8192

    const int smem_bytes = 2 * 3 * ROW_BYTES + 2 * 8 * sizeof(float2);  // 98432
    static int configured = 0;
    if (!configured) {
        cudaFuncSetAttribute(branch_route_kernel,
                             cudaFuncAttributeMaxDynamicSharedMemorySize,
                             smem_bytes);
        configured = 1;
    }

    const int grid = 148 * 2;          // 2 blocks/SM (96KB staging each)
    branch_route_kernel<<<grid, THREADS, smem_bytes>>>(x, gw, gb, out, N);
}